// round 1
// baseline (speedup 1.0000x reference)
#include <cuda_runtime.h>
#include <math.h>

#define BB 4
#define MM 8192
#define LL 64
#define DM 1024
#define IND 512
#define NH 8
#define DH 64
#define S_TOT (MM + LL)            // 8256
#define ROWS_X (BB * MM)           // 32768
#define ROWS_KV (BB * S_TOT)       // 33024
#define ROWS_L (BB * LL)           // 256
#define NCHUNK 17                  // ceil(8256/512)

// ---------------- scratch (static device globals; no allocation) ----------------
__device__ float g_mu[ROWS_X];
__device__ float g_rstd[ROWS_X];
__device__ float g_ln[ROWS_L * DM];                 // normalized latents
__device__ float g_kv[(size_t)ROWS_KV * 2 * IND];   // 135 MB
__device__ float g_q[ROWS_L * IND];
__device__ float g_po[BB * NH * NCHUNK * LL * DH];  // partial O (unnormalized)
__device__ float g_pm[BB * NH * NCHUNK * LL];       // partial row max
__device__ float g_pl[BB * NH * NCHUNK * LL];       // partial row sumexp
__device__ float g_ao[ROWS_L * IND];                // attention output [B*L][H*DH]

__device__ __forceinline__ float warpSum(float v) {
#pragma unroll
    for (int o = 16; o; o >>= 1) v += __shfl_xor_sync(0xffffffffu, v, o);
    return v;
}
__device__ __forceinline__ float warpMax(float v) {
#pragma unroll
    for (int o = 16; o; o >>= 1) v = fmaxf(v, __shfl_xor_sync(0xffffffffu, v, o));
    return v;
}

// ---------------- 1. LayerNorm stats (x) + full LN (latents) ----------------
__global__ void __launch_bounds__(256) ln_stats_kernel(
    const float* __restrict__ x, const float* __restrict__ lat,
    const float* __restrict__ gl, const float* __restrict__ bl)
{
    int row = blockIdx.x;          // 0..33023
    int tid = threadIdx.x;         // 256 threads, 4 floats each
    const float* src = (row < ROWS_X) ? (x + (size_t)row * DM)
                                      : (lat + (size_t)(row - ROWS_X) * DM);
    float4 v = reinterpret_cast<const float4*>(src)[tid];
    float s  = v.x + v.y + v.z + v.w;
    float sq = v.x * v.x + v.y * v.y + v.z * v.z + v.w * v.w;
    s  = warpSum(s);
    sq = warpSum(sq);
    __shared__ float sh[2][8];
    int w = tid >> 5, lane = tid & 31;
    if (lane == 0) { sh[0][w] = s; sh[1][w] = sq; }
    __syncthreads();
    float tot = 0.f, totq = 0.f;
#pragma unroll
    for (int i = 0; i < 8; i++) { tot += sh[0][i]; totq += sh[1][i]; }
    float mean = tot * (1.0f / 1024.0f);
    float var  = totq * (1.0f / 1024.0f) - mean * mean;
    float rstd = rsqrtf(var + 1e-5f);
    if (row < ROWS_X) {
        if (tid == 0) { g_mu[row] = mean; g_rstd[row] = rstd; }
    } else {
        int li = row - ROWS_X;
        float4 g4 = reinterpret_cast<const float4*>(gl)[tid];
        float4 b4 = reinterpret_cast<const float4*>(bl)[tid];
        float4 o;
        o.x = (v.x - mean) * rstd * g4.x + b4.x;
        o.y = (v.y - mean) * rstd * g4.y + b4.y;
        o.z = (v.z - mean) * rstd * g4.z + b4.z;
        o.w = (v.w - mean) * rstd * g4.w + b4.w;
        reinterpret_cast<float4*>(g_ln + (size_t)li * DM)[tid] = o;
    }
}

// ---------------- 2. q = ln @ Wq   (256 x 1024 @ 1024 x 512) ----------------
__global__ void __launch_bounds__(256) q_gemm_kernel(const float* __restrict__ Wq)
{
    int o = blockIdx.x * 256 + threadIdx.x;   // 32768 threads
    int n  = o & 511;
    int rg = o >> 9;                          // 0..63
    float a0 = 0.f, a1 = 0.f, a2 = 0.f, a3 = 0.f;
    const float* l0 = g_ln + (size_t)rg * DM;
    const float* l1 = g_ln + (size_t)(rg + 64) * DM;
    const float* l2 = g_ln + (size_t)(rg + 128) * DM;
    const float* l3 = g_ln + (size_t)(rg + 192) * DM;
    for (int k = 0; k < DM; k++) {
        float wv = __ldg(Wq + (size_t)k * IND + n);
        a0 += l0[k] * wv; a1 += l1[k] * wv; a2 += l2[k] * wv; a3 += l3[k] * wv;
    }
    g_q[(size_t)rg * IND + n]         = a0;
    g_q[(size_t)(rg + 64) * IND + n]  = a1;
    g_q[(size_t)(rg + 128) * IND + n] = a2;
    g_q[(size_t)(rg + 192) * IND + n] = a3;
}

// ---------------- 3. kv = LN(concat(x, ln)) @ Wkv  [33024x1024 @ 1024x1024] ----------------
// 128x128 block tile, BK=16, 256 threads, 8x8 micro-tile. LN fused into A load.
__global__ void __launch_bounds__(256) kv_gemm_kernel(
    const float* __restrict__ x, const float* __restrict__ Wkv,
    const float* __restrict__ gm, const float* __restrict__ bm)
{
    __shared__ float As[16][128];
    __shared__ float Ws[16][128];
    __shared__ float gsm[DM];
    __shared__ float bsm[DM];

    int tid = threadIdx.x;
    { // load gamma/beta once
        float4 g4 = reinterpret_cast<const float4*>(gm)[tid];
        float4 b4 = reinterpret_cast<const float4*>(bm)[tid];
        reinterpret_cast<float4*>(gsm)[tid] = g4;
        reinterpret_cast<float4*>(bsm)[tid] = b4;
    }

    // A-load mapping: one row per thread-pair, 8 consecutive k
    int ltrow = tid >> 1;
    int lk0   = (tid & 1) * 8;
    int grow  = blockIdx.y * 128 + ltrow;
    int bb_   = grow / S_TOT;
    int ss_   = grow - bb_ * S_TOT;
    const float* aptr;
    float mu = 0.f, rs = 1.f;
    bool isx;
    if (ss_ < MM) {
        isx = true;
        int xr = bb_ * MM + ss_;
        aptr = x + (size_t)xr * DM;
        mu = g_mu[xr]; rs = g_rstd[xr];
    } else {
        isx = false;
        aptr = g_ln + (size_t)(bb_ * LL + (ss_ - MM)) * DM;
    }

    // W-load mapping
    int wkk = tid >> 4;
    int wn0 = (tid & 15) * 8;
    const float* wptr = Wkv + (size_t)wkk * (2 * IND) + blockIdx.x * 128 + wn0;

    // compute mapping
    int ctr = (tid >> 4) * 8;
    int ctc = (tid & 15) * 8;

    float acc[8][8];
#pragma unroll
    for (int i = 0; i < 8; i++)
#pragma unroll
        for (int j = 0; j < 8; j++) acc[i][j] = 0.f;

    __syncthreads();   // gsm/bsm visible

    for (int k0 = 0; k0 < DM; k0 += 16) {
        // A tile (LN applied on the fly for x rows)
        float4 a0 = *reinterpret_cast<const float4*>(aptr + k0 + lk0);
        float4 a1 = *reinterpret_cast<const float4*>(aptr + k0 + lk0 + 4);
        if (isx) {
            int kb = k0 + lk0;
            a0.x = (a0.x - mu) * rs * gsm[kb + 0] + bsm[kb + 0];
            a0.y = (a0.y - mu) * rs * gsm[kb + 1] + bsm[kb + 1];
            a0.z = (a0.z - mu) * rs * gsm[kb + 2] + bsm[kb + 2];
            a0.w = (a0.w - mu) * rs * gsm[kb + 3] + bsm[kb + 3];
            a1.x = (a1.x - mu) * rs * gsm[kb + 4] + bsm[kb + 4];
            a1.y = (a1.y - mu) * rs * gsm[kb + 5] + bsm[kb + 5];
            a1.z = (a1.z - mu) * rs * gsm[kb + 6] + bsm[kb + 6];
            a1.w = (a1.w - mu) * rs * gsm[kb + 7] + bsm[kb + 7];
        }
        As[lk0 + 0][ltrow] = a0.x;
        As[lk0 + 1][ltrow] = a0.y;
        As[lk0 + 2][ltrow] = a0.z;
        As[lk0 + 3][ltrow] = a0.w;
        As[lk0 + 4][ltrow] = a1.x;
        As[lk0 + 5][ltrow] = a1.y;
        As[lk0 + 6][ltrow] = a1.z;
        As[lk0 + 7][ltrow] = a1.w;

        // W tile
        float4 w0 = *reinterpret_cast<const float4*>(wptr + (size_t)k0 * (2 * IND));
        float4 w1 = *reinterpret_cast<const float4*>(wptr + (size_t)k0 * (2 * IND) + 4);
        *reinterpret_cast<float4*>(&Ws[wkk][wn0])     = w0;
        *reinterpret_cast<float4*>(&Ws[wkk][wn0 + 4]) = w1;

        __syncthreads();

#pragma unroll
        for (int kk = 0; kk < 16; kk++) {
            float af[8], wf[8];
            *reinterpret_cast<float4*>(&af[0]) = *reinterpret_cast<const float4*>(&As[kk][ctr]);
            *reinterpret_cast<float4*>(&af[4]) = *reinterpret_cast<const float4*>(&As[kk][ctr + 4]);
            *reinterpret_cast<float4*>(&wf[0]) = *reinterpret_cast<const float4*>(&Ws[kk][ctc]);
            *reinterpret_cast<float4*>(&wf[4]) = *reinterpret_cast<const float4*>(&Ws[kk][ctc + 4]);
#pragma unroll
            for (int i = 0; i < 8; i++)
#pragma unroll
                for (int j = 0; j < 8; j++) acc[i][j] += af[i] * wf[j];
        }
        __syncthreads();
    }

    int orow = blockIdx.y * 128 + ctr;
    int ocol = blockIdx.x * 128 + ctc;
#pragma unroll
    for (int i = 0; i < 8; i++) {
        float4 o0 = make_float4(acc[i][0], acc[i][1], acc[i][2], acc[i][3]);
        float4 o1 = make_float4(acc[i][4], acc[i][5], acc[i][6], acc[i][7]);
        *reinterpret_cast<float4*>(g_kv + (size_t)(orow + i) * (2 * IND) + ocol)     = o0;
        *reinterpret_cast<float4*>(g_kv + (size_t)(orow + i) * (2 * IND) + ocol + 4) = o1;
    }
}

// ---------------- 4. split-KV flash attention ----------------
// grid (NCHUNK, 32). 256 threads = 8 warps; warp owns 8 q-rows; lane owns 1 key per 32-key tile.
__global__ void __launch_bounds__(256) attn_kernel()
{
    __shared__ float Qs[64][64];
    __shared__ float KT[64][33];   // padded
    __shared__ float Vs[32][64];

    int bh = blockIdx.y;
    int b = bh >> 3, h = bh & 7;
    int tid = threadIdx.x, w = tid >> 5, lane = tid & 31;

    for (int i = tid; i < 64 * 64; i += 256) {
        int row = i >> 6, d = i & 63;
        // q / scale with scale = dh^-0.5  ->  * sqrt(64) = 8
        Qs[row][d] = g_q[(size_t)(b * 64 + row) * IND + h * 64 + d] * 8.0f;
    }

    float m[8], l[8], o1[8], o2[8];
#pragma unroll
    for (int r = 0; r < 8; r++) { m[r] = -3.0e38f; l[r] = 0.f; o1[r] = 0.f; o2[r] = 0.f; }

    int s0beg = blockIdx.x * 512;
    int s0end = min(S_TOT, s0beg + 512);
    int key = tid >> 3;          // 0..31
    int d0  = (tid & 7) * 8;

    for (int s0 = s0beg; s0 < s0end; s0 += 32) {
        __syncthreads();
        const float* kp = g_kv + ((size_t)(b * S_TOT + s0 + key)) * (2 * IND) + h * 64 + d0;
        float4 k0 = *reinterpret_cast<const float4*>(kp);
        float4 k1 = *reinterpret_cast<const float4*>(kp + 4);
        KT[d0 + 0][key] = k0.x; KT[d0 + 1][key] = k0.y;
        KT[d0 + 2][key] = k0.z; KT[d0 + 3][key] = k0.w;
        KT[d0 + 4][key] = k1.x; KT[d0 + 5][key] = k1.y;
        KT[d0 + 6][key] = k1.z; KT[d0 + 7][key] = k1.w;
        const float* vp = kp + IND;
        float4 v0 = *reinterpret_cast<const float4*>(vp);
        float4 v1 = *reinterpret_cast<const float4*>(vp + 4);
        *reinterpret_cast<float4*>(&Vs[key][d0])     = v0;
        *reinterpret_cast<float4*>(&Vs[key][d0 + 4]) = v1;
        __syncthreads();

#pragma unroll
        for (int r = 0; r < 8; r++) {
            int row = (w << 3) + r;
            float s = 0.f;
#pragma unroll
            for (int d = 0; d < 64; d++) s += Qs[row][d] * KT[d][lane];
            float tm = warpMax(s);
            float mn = fmaxf(m[r], tm);
            float p     = __expf(s - mn);
            float alpha = __expf(m[r] - mn);
            float psum  = warpSum(p);
            l[r] = l[r] * alpha + psum;
            m[r] = mn;
            float a1 = o1[r] * alpha;
            float a2 = o2[r] * alpha;
#pragma unroll
            for (int ss = 0; ss < 32; ss++) {
                float pv = __shfl_sync(0xffffffffu, p, ss);
                a1 += pv * Vs[ss][lane];
                a2 += pv * Vs[ss][lane + 32];
            }
            o1[r] = a1; o2[r] = a2;
        }
    }

    int c = bh * NCHUNK + blockIdx.x;
#pragma unroll
    for (int r = 0; r < 8; r++) {
        int row = (w << 3) + r;
        size_t base = ((size_t)c * 64 + row) * 64;
        g_po[base + lane]      = o1[r];
        g_po[base + lane + 32] = o2[r];
        if (lane == 0) { g_pm[c * 64 + row] = m[r]; g_pl[c * 64 + row] = l[r]; }
    }
}

// ---------------- 5. merge split-KV partials ----------------
__global__ void __launch_bounds__(256) merge_kernel()
{
    int bh = blockIdx.x;
    int b = bh >> 3, h = bh & 7;
    int tid = threadIdx.x;
    int row = tid >> 2;
    int dp  = (tid & 3) * 16;

    float mx = -3.0e38f;
    for (int c = 0; c < NCHUNK; c++)
        mx = fmaxf(mx, g_pm[(bh * NCHUNK + c) * 64 + row]);

    float Ls = 0.f;
    float acc[16];
#pragma unroll
    for (int j = 0; j < 16; j++) acc[j] = 0.f;

    for (int c = 0; c < NCHUNK; c++) {
        int idx = (bh * NCHUNK + c) * 64 + row;
        float wgt = __expf(g_pm[idx] - mx);
        Ls += wgt * g_pl[idx];
        const float* po = g_po + (size_t)idx * 64 + dp;
#pragma unroll
        for (int j = 0; j < 16; j++) acc[j] += wgt * po[j];
    }
    float inv = 1.0f / Ls;
    float* dst = g_ao + (size_t)(b * 64 + row) * IND + h * 64 + dp;
#pragma unroll
    for (int j = 0; j < 16; j++) dst[j] = acc[j] * inv;
}

// ---------------- 6. out = attn_out @ Wout  (256 x 512 @ 512 x 1024) ----------------
__global__ void __launch_bounds__(256) out_gemm_kernel(
    const float* __restrict__ Wout, float* __restrict__ out)
{
    int o = blockIdx.x * 256 + threadIdx.x;   // 65536 threads
    int n  = o & 1023;
    int rg = o >> 10;                         // 0..63
    float a0 = 0.f, a1 = 0.f, a2 = 0.f, a3 = 0.f;
    const float* l0 = g_ao + (size_t)rg * IND;
    const float* l1 = g_ao + (size_t)(rg + 64) * IND;
    const float* l2 = g_ao + (size_t)(rg + 128) * IND;
    const float* l3 = g_ao + (size_t)(rg + 192) * IND;
    for (int k = 0; k < IND; k++) {
        float wv = __ldg(Wout + (size_t)k * DM + n);
        a0 += l0[k] * wv; a1 += l1[k] * wv; a2 += l2[k] * wv; a3 += l3[k] * wv;
    }
    out[(size_t)rg * DM + n]         = a0;
    out[(size_t)(rg + 64) * DM + n]  = a1;
    out[(size_t)(rg + 128) * DM + n] = a2;
    out[(size_t)(rg + 192) * DM + n] = a3;
}

// ---------------- launch ----------------
extern "C" void kernel_launch(void* const* d_in, const int* in_sizes, int n_in,
                              void* d_out, int out_size)
{
    const float* x    = (const float*)d_in[0];
    const float* lat  = (const float*)d_in[1];
    const float* Wq   = (const float*)d_in[2];
    const float* Wkv  = (const float*)d_in[3];
    const float* Wout = (const float*)d_in[4];
    const float* gm   = (const float*)d_in[5];
    const float* bm   = (const float*)d_in[6];
    const float* gl   = (const float*)d_in[7];
    const float* bl   = (const float*)d_in[8];
    float* out = (float*)d_out;

    ln_stats_kernel<<<ROWS_KV, 256>>>(x, lat, gl, bl);
    q_gemm_kernel<<<32768 / 256, 256>>>(Wq);
    kv_gemm_kernel<<<dim3(8, 258), 256>>>(x, Wkv, gm, bm);
    attn_kernel<<<dim3(NCHUNK, 32), 256>>>();
    merge_kernel<<<32, 256>>>();
    out_gemm_kernel<<<65536 / 256, 256>>>(Wout, out);
}

// round 3
// speedup vs baseline: 1.9538x; 1.9538x over previous
#include <cuda_runtime.h>
#include <cuda_bf16.h>
#include <stdint.h>
#include <math.h>

#define BB 4
#define MM 8192
#define LL 64
#define DM 1024
#define IND 512
#define NH 8
#define DH 64
#define S_TOT (MM + LL)            // 8256
#define ROWS_X (BB * MM)           // 32768
#define ROWS_KV (BB * S_TOT)       // 33024
#define ROWS_L (BB * LL)           // 256
#define NCHUNK 17                  // ceil(8256/512)

// ---------------- scratch ----------------
__device__ float g_ln[ROWS_L * DM];                 // normalized latents (fp32)
__device__ __nv_bfloat16 g_Ahi[(size_t)ROWS_KV * DM];
__device__ __nv_bfloat16 g_Alo[(size_t)ROWS_KV * DM];
__device__ __nv_bfloat16 g_Whi[(size_t)DM * DM];    // transposed: [n][k]
__device__ __nv_bfloat16 g_Wlo[(size_t)DM * DM];
__device__ float g_kv[(size_t)ROWS_KV * 2 * IND];   // 135 MB
__device__ float g_q[ROWS_L * IND];
__device__ float g_po[BB * NH * NCHUNK * LL * DH];
__device__ float g_pm[BB * NH * NCHUNK * LL];
__device__ float g_pl[BB * NH * NCHUNK * LL];
__device__ float g_ao[ROWS_L * IND];

__device__ __forceinline__ float warpSum(float v) {
#pragma unroll
    for (int o = 16; o; o >>= 1) v += __shfl_xor_sync(0xffffffffu, v, o);
    return v;
}
__device__ __forceinline__ float warpMax(float v) {
#pragma unroll
    for (int o = 16; o; o >>= 1) v = fmaxf(v, __shfl_xor_sync(0xffffffffu, v, o));
    return v;
}

// ---------------- PTX helpers (tcgen05 only valid on sm_103a pass) ----------------
__device__ __forceinline__ uint32_t smem_u32(const void* p) {
    uint32_t a;
    asm("{ .reg .u64 t; cvta.to.shared.u64 t, %1; cvt.u32.u64 %0, t; }" : "=r"(a) : "l"(p));
    return a;
}
__device__ __forceinline__ uint32_t elect_one() {
    uint32_t pred;
    asm volatile("{\n\t.reg .pred p;\n\telect.sync _|p, 0xFFFFFFFF;\n\tselp.b32 %0, 1, 0, p;\n\t}" : "=r"(pred));
    return pred;
}
#define MBAR_INIT(addr, cnt) \
    asm volatile("mbarrier.init.shared.b64 [%0], %1;" :: "r"(addr), "r"(cnt) : "memory")
#define MBAR_WAIT(addr, parity) do { \
    uint32_t _m = (addr); uint32_t _p = (parity); uint32_t _done; \
    asm volatile("{\n\t.reg .pred p;\n\tmbarrier.try_wait.parity.acquire.cta.shared::cta.b64 p, [%1], %2;\n\tselp.b32 %0, 1, 0, p;\n\t}" \
        : "=r"(_done) : "r"(_m), "r"(_p) : "memory"); \
    if (!_done) { \
        asm volatile("{\n\t.reg .pred P1;\n\tWL_%=:\n\tmbarrier.try_wait.parity.acquire.cta.shared::cta.b64 P1, [%0], %1, 0x989680;\n\t@P1 bra.uni WD_%=;\n\tbra.uni WL_%=;\n\tWD_%=:\n\t}" \
            :: "r"(_m), "r"(_p) : "memory"); \
    } } while (0)
#define FENCE_ASYNC() asm volatile("fence.proxy.async.shared::cta;" ::: "memory")

#if defined(__CUDA_ARCH_FEAT_SM103_ALL) || defined(__CUDA_ARCH_FEAT_SM100_ALL)
#define HAS_TCGEN05 1
#else
#define HAS_TCGEN05 0
#endif

#if HAS_TCGEN05
#define TC_ALLOC(smem_addr, ncols) \
    asm volatile("tcgen05.alloc.cta_group::1.sync.aligned.shared::cta.b32 [%0], %1;" :: "r"(smem_addr), "r"(ncols) : "memory")
#define TC_DEALLOC(tmem, ncols) \
    asm volatile("tcgen05.dealloc.cta_group::1.sync.aligned.b32 %0, %1;" :: "r"(tmem), "r"(ncols))
#define TC_RELINQ() \
    asm volatile("tcgen05.relinquish_alloc_permit.cta_group::1.sync.aligned;")
#define TC_COMMIT(mbar) \
    asm volatile("tcgen05.commit.cta_group::1.mbarrier::arrive::one.shared::cluster.b64 [%0];" :: "r"(mbar) : "memory")
#define TC_FENCE_AFTER() asm volatile("tcgen05.fence::after_thread_sync;" ::: "memory")
#define TC_WAIT_LD() asm volatile("tcgen05.wait::ld.sync.aligned;" ::: "memory")

__device__ __forceinline__ void mma_f16_ss(uint32_t d, uint64_t ad, uint64_t bd,
                                           uint32_t idesc, uint32_t en) {
    asm volatile(
        "{\n\t.reg .pred p;\n\tsetp.ne.u32 p, %4, 0;\n\t"
        "tcgen05.mma.cta_group::1.kind::f16 [%0], %1, %2, %3, {%5, %5, %5, %5}, p;\n\t}"
        :: "r"(d), "l"(ad), "l"(bd), "r"(idesc), "r"(en), "r"(0u) : "memory");
}
#define LDTM_X32(r, addr) \
    asm volatile("tcgen05.ld.sync.aligned.32x32b.x32.b32 " \
        "{%0,%1,%2,%3,%4,%5,%6,%7,%8,%9,%10,%11,%12,%13,%14,%15," \
        "%16,%17,%18,%19,%20,%21,%22,%23,%24,%25,%26,%27,%28,%29,%30,%31}, [%32];" \
        : "=r"((r)[0]),"=r"((r)[1]),"=r"((r)[2]),"=r"((r)[3]),"=r"((r)[4]),"=r"((r)[5]),"=r"((r)[6]),"=r"((r)[7]), \
          "=r"((r)[8]),"=r"((r)[9]),"=r"((r)[10]),"=r"((r)[11]),"=r"((r)[12]),"=r"((r)[13]),"=r"((r)[14]),"=r"((r)[15]), \
          "=r"((r)[16]),"=r"((r)[17]),"=r"((r)[18]),"=r"((r)[19]),"=r"((r)[20]),"=r"((r)[21]),"=r"((r)[22]),"=r"((r)[23]), \
          "=r"((r)[24]),"=r"((r)[25]),"=r"((r)[26]),"=r"((r)[27]),"=r"((r)[28]),"=r"((r)[29]),"=r"((r)[30]),"=r"((r)[31]) \
        : "r"(addr))
#endif

// SW128 desc: layout=2, version=1, SBO=64, LBO=1
__device__ __forceinline__ uint64_t make_desc(uint32_t saddr) {
    const uint64_t base = (uint64_t(2) << 61) | (uint64_t(1) << 46) | (uint64_t(64) << 32) | (uint64_t(1) << 16);
    return base | ((uint64_t)(saddr >> 4) & 0x3FFF);
}

// idesc: F32 accum, BF16 a/b, N=256, M=128
#define KV_IDESC ((1u << 4) | (1u << 7) | (1u << 10) | (32u << 17) | (8u << 24))

// ---------------- 1. LN + bf16 hi/lo split of A = concat(xn, ln) ----------------
__global__ void __launch_bounds__(256) prep_a_kernel(
    const float* __restrict__ x, const float* __restrict__ lat,
    const float* __restrict__ gm, const float* __restrict__ bm,
    const float* __restrict__ gl, const float* __restrict__ bl)
{
    int row = blockIdx.x;          // 0..33023
    int tid = threadIdx.x;
    bool isx = row < ROWS_X;
    const float* src = isx ? (x + (size_t)row * DM)
                           : (lat + (size_t)(row - ROWS_X) * DM);
    float4 v = reinterpret_cast<const float4*>(src)[tid];
    float s  = v.x + v.y + v.z + v.w;
    float sq = v.x * v.x + v.y * v.y + v.z * v.z + v.w * v.w;
    s = warpSum(s); sq = warpSum(sq);
    __shared__ float sh[2][8];
    int w = tid >> 5, lane = tid & 31;
    if (lane == 0) { sh[0][w] = s; sh[1][w] = sq; }
    __syncthreads();
    float tot = 0.f, totq = 0.f;
#pragma unroll
    for (int i = 0; i < 8; i++) { tot += sh[0][i]; totq += sh[1][i]; }
    float mean = tot * (1.0f / 1024.0f);
    float var  = totq * (1.0f / 1024.0f) - mean * mean;
    float rstd = rsqrtf(var + 1e-5f);

    const float* gp = isx ? gm : gl;
    const float* bp = isx ? bm : bl;
    float4 g4 = reinterpret_cast<const float4*>(gp)[tid];
    float4 b4 = reinterpret_cast<const float4*>(bp)[tid];
    float4 o;
    o.x = (v.x - mean) * rstd * g4.x + b4.x;
    o.y = (v.y - mean) * rstd * g4.y + b4.y;
    o.z = (v.z - mean) * rstd * g4.z + b4.z;
    o.w = (v.w - mean) * rstd * g4.w + b4.w;

    int arow;
    if (isx) {
        int bb = row >> 13, ss = row & 8191;
        arow = bb * S_TOT + ss;
    } else {
        int lr = row - ROWS_X;
        int bb = lr >> 6, j = lr & 63;
        arow = bb * S_TOT + MM + j;
        reinterpret_cast<float4*>(g_ln + (size_t)lr * DM)[tid] = o;
    }
    // split hi/lo
    __nv_bfloat16 hx = __float2bfloat16(o.x), hy = __float2bfloat16(o.y);
    __nv_bfloat16 hz = __float2bfloat16(o.z), hw = __float2bfloat16(o.w);
    float rx = o.x - __bfloat162float(hx), ry = o.y - __bfloat162float(hy);
    float rz = o.z - __bfloat162float(hz), rw = o.w - __bfloat162float(hw);
    __nv_bfloat162 h01 = __nv_bfloat162(hx, hy), h23 = __nv_bfloat162(hz, hw);
    __nv_bfloat162 l01 = __floats2bfloat162_rn(rx, ry), l23 = __floats2bfloat162_rn(rz, rw);
    uint2 uh, ul;
    uh.x = *reinterpret_cast<uint32_t*>(&h01); uh.y = *reinterpret_cast<uint32_t*>(&h23);
    ul.x = *reinterpret_cast<uint32_t*>(&l01); ul.y = *reinterpret_cast<uint32_t*>(&l23);
    reinterpret_cast<uint2*>(g_Ahi + (size_t)arow * DM)[tid] = uh;
    reinterpret_cast<uint2*>(g_Alo + (size_t)arow * DM)[tid] = ul;
}

// ---------------- 2. W transpose + hi/lo split ----------------
__global__ void __launch_bounds__(256) prep_w_kernel(const float* __restrict__ Wkv)
{
    int n = blockIdx.x;            // 0..1023
    for (int k = threadIdx.x; k < DM; k += 256) {
        float wv = Wkv[(size_t)k * (2 * IND) + n];
        __nv_bfloat16 hi = __float2bfloat16(wv);
        float r = wv - __bfloat162float(hi);
        g_Whi[(size_t)n * DM + k] = hi;
        g_Wlo[(size_t)n * DM + k] = __float2bfloat16(r);
    }
}

// ---------------- 3. q = ln @ Wq ----------------
__global__ void __launch_bounds__(256) q_gemm_kernel(const float* __restrict__ Wq)
{
    int o = blockIdx.x * 256 + threadIdx.x;
    int n  = o & 511;
    int rg = o >> 9;
    float a0 = 0.f, a1 = 0.f, a2 = 0.f, a3 = 0.f;
    const float* l0 = g_ln + (size_t)rg * DM;
    const float* l1 = g_ln + (size_t)(rg + 64) * DM;
    const float* l2 = g_ln + (size_t)(rg + 128) * DM;
    const float* l3 = g_ln + (size_t)(rg + 192) * DM;
    for (int k = 0; k < DM; k++) {
        float wv = __ldg(Wq + (size_t)k * IND + n);
        a0 += l0[k] * wv; a1 += l1[k] * wv; a2 += l2[k] * wv; a3 += l3[k] * wv;
    }
    g_q[(size_t)rg * IND + n]         = a0;
    g_q[(size_t)(rg + 64) * IND + n]  = a1;
    g_q[(size_t)(rg + 128) * IND + n] = a2;
    g_q[(size_t)(rg + 192) * IND + n] = a3;
}

// ---------------- 4. KV GEMM on tcgen05 (split-bf16, fp32 accum) ----------------
// grid (4 ntiles, 258 mtiles), 256 threads. CTA tile: M=128, N=256.
// Loop: 16 k-chunks A=Ahi vs {Whi, Wlo}, then 16 chunks A=Alo vs {Whi}. K chunk = 64.
#define SM_TM   0
#define SM_MB   64
#define SM_A    1024
#define SM_B    (1024 + 2 * 16384)
#define SM_TOT  (SM_B + 4 * 32768)

__global__ void __launch_bounds__(256) kv_gemm_tc()
{
#if HAS_TCGEN05
    extern __shared__ char smem[];
    uint32_t sb = smem_u32(smem);
    int tid = threadIdx.x, wid = tid >> 5;
    int ntile = blockIdx.x, mtile = blockIdx.y;

    if (wid == 0) { TC_ALLOC(sb + SM_TM, 256); TC_RELINQ(); }
    if (tid == 0) { MBAR_INIT(sb + SM_MB, 1); MBAR_INIT(sb + SM_MB + 8, 1); }
    __syncthreads();
    uint32_t tmem;
    asm volatile("ld.shared.b32 %0, [%1];" : "=r"(tmem) : "r"(sb + SM_TM));

    int pcs[2] = {0, 0};

    for (int c = 0; c < 32; c++) {
        int stage = c & 1;
        int pass  = c >> 4;          // 0: Ahi, 1: Alo
        int kc    = c & 15;

        if (c >= 2) { MBAR_WAIT(sb + SM_MB + stage * 8, (uint32_t)(pcs[stage] & 1)); pcs[stage]++; }

        // A tile: 128 rows x 128B
        {
            const char* Ab = pass ? (const char*)g_Alo : (const char*)g_Ahi;
            const char* base = Ab + (size_t)(mtile * 128) * 2048 + kc * 128;
#pragma unroll
            for (int it = 0; it < 4; it++) {
                int idx = it * 256 + tid;
                int row = idx >> 3, cb = idx & 7;
                uint4 v = *reinterpret_cast<const uint4*>(base + (size_t)row * 2048 + cb * 16);
                uint32_t bo = (uint32_t)(row * 128 + cb * 16);
                bo ^= ((bo >> 3) & 0x70);
                *reinterpret_cast<uint4*>(smem + SM_A + stage * 16384 + bo) = v;
            }
        }
        // B tiles: 256 rows x 128B each
        int nB = pass ? 1 : 2;
        for (int t = 0; t < nB; t++) {
            const char* Wb = t ? (const char*)g_Wlo : (const char*)g_Whi;
            const char* base = Wb + (size_t)(ntile * 256) * 2048 + kc * 128;
#pragma unroll
            for (int it = 0; it < 8; it++) {
                int idx = it * 256 + tid;
                int row = idx >> 3, cb = idx & 7;
                uint4 v = *reinterpret_cast<const uint4*>(base + (size_t)row * 2048 + cb * 16);
                uint32_t bo = (uint32_t)(row * 128 + cb * 16);
                bo ^= ((bo >> 3) & 0x70);
                *reinterpret_cast<uint4*>(smem + SM_B + (stage * 2 + t) * 32768 + bo) = v;
            }
        }
        FENCE_ASYNC();
        __syncthreads();

        if (wid == 0 && elect_one()) {
            uint64_t ad = make_desc(sb + SM_A + stage * 16384);
#pragma unroll
            for (int t = 0; t < 2; t++) {
                if (t >= nB) break;
                uint64_t bd = make_desc(sb + SM_B + (stage * 2 + t) * 32768);
#pragma unroll
                for (int s = 0; s < 4; s++) {
                    uint32_t en = !(c == 0 && t == 0 && s == 0);
                    mma_f16_ss(tmem, ad + s * 2, bd + s * 2, KV_IDESC, en);
                }
            }
            TC_COMMIT(sb + SM_MB + stage * 8);
        }
    }

    MBAR_WAIT(sb + SM_MB,     (uint32_t)(pcs[0] & 1));
    MBAR_WAIT(sb + SM_MB + 8, (uint32_t)(pcs[1] & 1));
    TC_FENCE_AFTER();

    if (wid < 4) {
        int lane = tid & 31;
        size_t rowg = (size_t)(mtile * 128 + wid * 32 + lane);
        float* dst = g_kv + rowg * (2 * IND) + ntile * 256;
#pragma unroll
        for (int cb = 0; cb < 8; cb++) {
            uint32_t r[32];
            LDTM_X32(r, tmem + cb * 32);
            TC_WAIT_LD();
#pragma unroll
            for (int j = 0; j < 32; j += 4) {
                uint4 v;
                v.x = r[j]; v.y = r[j + 1]; v.z = r[j + 2]; v.w = r[j + 3];
                *reinterpret_cast<uint4*>(dst + cb * 32 + j) = v;
            }
        }
    }
    __syncthreads();
    if (wid == 0) TC_DEALLOC(tmem, 256);
#else
    // Fallback for the generic compute_103 PTX pass (never executed on sm_103a:
    // the exact-arch cubin takes precedence). Slow but correct.
    int tid = threadIdx.x;
    int ntile = blockIdx.x, mtile = blockIdx.y;
    for (int i = tid; i < 128 * 256; i += 256) {
        int r = i >> 8, cc = i & 255;
        size_t row = (size_t)mtile * 128 + r;
        size_t col = (size_t)ntile * 256 + cc;
        float acc = 0.f;
        for (int k = 0; k < DM; k++) {
            float a = __bfloat162float(g_Ahi[row * DM + k]) + __bfloat162float(g_Alo[row * DM + k]);
            float w = __bfloat162float(g_Whi[col * DM + k]) + __bfloat162float(g_Wlo[col * DM + k]);
            acc += a * w;
        }
        g_kv[row * (2 * IND) + col] = acc;
    }
#endif
}

// ---------------- 5. split-KV flash attention ----------------
__global__ void __launch_bounds__(256) attn_kernel()
{
    __shared__ float Qs[64][64];
    __shared__ float KT[64][33];
    __shared__ float Vs[32][64];

    int bh = blockIdx.y;
    int b = bh >> 3, h = bh & 7;
    int tid = threadIdx.x, w = tid >> 5, lane = tid & 31;

    for (int i = tid; i < 64 * 64; i += 256) {
        int row = i >> 6, d = i & 63;
        Qs[row][d] = g_q[(size_t)(b * 64 + row) * IND + h * 64 + d] * 8.0f;
    }

    float m[8], l[8], o1[8], o2[8];
#pragma unroll
    for (int r = 0; r < 8; r++) { m[r] = -3.0e38f; l[r] = 0.f; o1[r] = 0.f; o2[r] = 0.f; }

    int s0beg = blockIdx.x * 512;
    int s0end = min(S_TOT, s0beg + 512);
    int key = tid >> 3;
    int d0  = (tid & 7) * 8;

    for (int s0 = s0beg; s0 < s0end; s0 += 32) {
        __syncthreads();
        const float* kp = g_kv + ((size_t)(b * S_TOT + s0 + key)) * (2 * IND) + h * 64 + d0;
        float4 k0 = *reinterpret_cast<const float4*>(kp);
        float4 k1 = *reinterpret_cast<const float4*>(kp + 4);
        KT[d0 + 0][key] = k0.x; KT[d0 + 1][key] = k0.y;
        KT[d0 + 2][key] = k0.z; KT[d0 + 3][key] = k0.w;
        KT[d0 + 4][key] = k1.x; KT[d0 + 5][key] = k1.y;
        KT[d0 + 6][key] = k1.z; KT[d0 + 7][key] = k1.w;
        const float* vp = kp + IND;
        float4 v0 = *reinterpret_cast<const float4*>(vp);
        float4 v1 = *reinterpret_cast<const float4*>(vp + 4);
        *reinterpret_cast<float4*>(&Vs[key][d0])     = v0;
        *reinterpret_cast<float4*>(&Vs[key][d0 + 4]) = v1;
        __syncthreads();

#pragma unroll
        for (int r = 0; r < 8; r++) {
            int row = (w << 3) + r;
            float s = 0.f;
#pragma unroll
            for (int d = 0; d < 64; d++) s += Qs[row][d] * KT[d][lane];
            float tm = warpMax(s);
            float mn = fmaxf(m[r], tm);
            float p     = __expf(s - mn);
            float alpha = __expf(m[r] - mn);
            float psum  = warpSum(p);
            l[r] = l[r] * alpha + psum;
            m[r] = mn;
            float a1 = o1[r] * alpha;
            float a2 = o2[r] * alpha;
#pragma unroll
            for (int ss = 0; ss < 32; ss++) {
                float pv = __shfl_sync(0xffffffffu, p, ss);
                a1 += pv * Vs[ss][lane];
                a2 += pv * Vs[ss][lane + 32];
            }
            o1[r] = a1; o2[r] = a2;
        }
    }

    int c = bh * NCHUNK + blockIdx.x;
#pragma unroll
    for (int r = 0; r < 8; r++) {
        int row = (w << 3) + r;
        size_t base = ((size_t)c * 64 + row) * 64;
        g_po[base + lane]      = o1[r];
        g_po[base + lane + 32] = o2[r];
        if (lane == 0) { g_pm[c * 64 + row] = m[r]; g_pl[c * 64 + row] = l[r]; }
    }
}

// ---------------- 6. merge split-KV partials ----------------
__global__ void __launch_bounds__(256) merge_kernel()
{
    int bh = blockIdx.x;
    int b = bh >> 3, h = bh & 7;
    int tid = threadIdx.x;
    int row = tid >> 2;
    int dp  = (tid & 3) * 16;

    float mx = -3.0e38f;
    for (int c = 0; c < NCHUNK; c++)
        mx = fmaxf(mx, g_pm[(bh * NCHUNK + c) * 64 + row]);

    float Ls = 0.f;
    float acc[16];
#pragma unroll
    for (int j = 0; j < 16; j++) acc[j] = 0.f;

    for (int c = 0; c < NCHUNK; c++) {
        int idx = (bh * NCHUNK + c) * 64 + row;
        float wgt = __expf(g_pm[idx] - mx);
        Ls += wgt * g_pl[idx];
        const float* po = g_po + (size_t)idx * 64 + dp;
#pragma unroll
        for (int j = 0; j < 16; j++) acc[j] += wgt * po[j];
    }
    float inv = 1.0f / Ls;
    float* dst = g_ao + (size_t)(b * 64 + row) * IND + h * 64 + dp;
#pragma unroll
    for (int j = 0; j < 16; j++) dst[j] = acc[j] * inv;
}

// ---------------- 7. out = attn_out @ Wout ----------------
__global__ void __launch_bounds__(256) out_gemm_kernel(
    const float* __restrict__ Wout, float* __restrict__ out)
{
    int o = blockIdx.x * 256 + threadIdx.x;
    int n  = o & 1023;
    int rg = o >> 10;
    float a0 = 0.f, a1 = 0.f, a2 = 0.f, a3 = 0.f;
    const float* l0 = g_ao + (size_t)rg * IND;
    const float* l1 = g_ao + (size_t)(rg + 64) * IND;
    const float* l2 = g_ao + (size_t)(rg + 128) * IND;
    const float* l3 = g_ao + (size_t)(rg + 192) * IND;
    for (int k = 0; k < IND; k++) {
        float wv = __ldg(Wout + (size_t)k * DM + n);
        a0 += l0[k] * wv; a1 += l1[k] * wv; a2 += l2[k] * wv; a3 += l3[k] * wv;
    }
    out[(size_t)rg * DM + n]         = a0;
    out[(size_t)(rg + 64) * DM + n]  = a1;
    out[(size_t)(rg + 128) * DM + n] = a2;
    out[(size_t)(rg + 192) * DM + n] = a3;
}

// ---------------- launch ----------------
extern "C" void kernel_launch(void* const* d_in, const int* in_sizes, int n_in,
                              void* d_out, int out_size)
{
    const float* x    = (const float*)d_in[0];
    const float* lat  = (const float*)d_in[1];
    const float* Wq   = (const float*)d_in[2];
    const float* Wkv  = (const float*)d_in[3];
    const float* Wout = (const float*)d_in[4];
    const float* gm   = (const float*)d_in[5];
    const float* bm   = (const float*)d_in[6];
    const float* gl   = (const float*)d_in[7];
    const float* bl   = (const float*)d_in[8];
    float* out = (float*)d_out;

    cudaFuncSetAttribute(kv_gemm_tc, cudaFuncAttributeMaxDynamicSharedMemorySize, SM_TOT);

    prep_a_kernel<<<ROWS_KV, 256>>>(x, lat, gm, bm, gl, bl);
    prep_w_kernel<<<DM, 256>>>(Wkv);
    q_gemm_kernel<<<32768 / 256, 256>>>(Wq);
    kv_gemm_tc<<<dim3(4, 258), 256, SM_TOT>>>();
    attn_kernel<<<dim3(NCHUNK, 32), 256>>>();
    merge_kernel<<<32, 256>>>();
    out_gemm_kernel<<<65536 / 256, 256>>>(Wout, out);
}

// round 4
// speedup vs baseline: 2.6440x; 1.3533x over previous
#include <cuda_runtime.h>
#include <cuda_bf16.h>
#include <stdint.h>
#include <math.h>

#define BB 4
#define MM 8192
#define LL 64
#define DM 1024
#define IND 512
#define NH 8
#define DH 64
#define S_TOT (MM + LL)            // 8256
#define ROWS_X (BB * MM)           // 32768
#define ROWS_KV (BB * S_TOT)       // 33024
#define ROWS_L (BB * LL)           // 256
#define NCHUNK 17                  // ceil(8256/512)

// ---------------- scratch ----------------
__device__ float g_ln[ROWS_L * DM];
__device__ __nv_bfloat16 g_Ahi[(size_t)ROWS_KV * DM];
__device__ __nv_bfloat16 g_Alo[(size_t)ROWS_KV * DM];
__device__ __nv_bfloat16 g_Whi[(size_t)DM * DM];    // transposed: [n][k]
__device__ __nv_bfloat16 g_Wlo[(size_t)DM * DM];
__device__ float g_kv[(size_t)ROWS_KV * 2 * IND];
__device__ float g_q[ROWS_L * IND];
__device__ float g_po[BB * NH * NCHUNK * LL * DH];
__device__ float g_pm[BB * NH * NCHUNK * LL];
__device__ float g_pl[BB * NH * NCHUNK * LL];
__device__ float g_ao[ROWS_L * IND];

__device__ __forceinline__ float warpSum(float v) {
#pragma unroll
    for (int o = 16; o; o >>= 1) v += __shfl_xor_sync(0xffffffffu, v, o);
    return v;
}
__device__ __forceinline__ float warpMax(float v) {
#pragma unroll
    for (int o = 16; o; o >>= 1) v = fmaxf(v, __shfl_xor_sync(0xffffffffu, v, o));
    return v;
}

// ---------------- PTX helpers ----------------
__device__ __forceinline__ uint32_t smem_u32(const void* p) {
    uint32_t a;
    asm("{ .reg .u64 t; cvta.to.shared.u64 t, %1; cvt.u32.u64 %0, t; }" : "=r"(a) : "l"(p));
    return a;
}
__device__ __forceinline__ uint32_t elect_one() {
    uint32_t pred;
    asm volatile("{\n\t.reg .pred p;\n\telect.sync _|p, 0xFFFFFFFF;\n\tselp.b32 %0, 1, 0, p;\n\t}" : "=r"(pred));
    return pred;
}
__device__ __forceinline__ void cp16(uint32_t dst, const void* src) {
    asm volatile("cp.async.cg.shared.global [%0], [%1], 16;" :: "r"(dst), "l"(src));
}
#define CP_COMMIT() asm volatile("cp.async.commit_group;" ::: "memory")
#define CP_WAIT(n)  asm volatile("cp.async.wait_group %0;" :: "n"(n) : "memory")
#define MBAR_INIT(addr, cnt) \
    asm volatile("mbarrier.init.shared.b64 [%0], %1;" :: "r"(addr), "r"(cnt) : "memory")
#define MBAR_WAIT(addr, parity) do { \
    uint32_t _m = (addr); uint32_t _p = (parity); uint32_t _done; \
    asm volatile("{\n\t.reg .pred p;\n\tmbarrier.try_wait.parity.acquire.cta.shared::cta.b64 p, [%1], %2;\n\tselp.b32 %0, 1, 0, p;\n\t}" \
        : "=r"(_done) : "r"(_m), "r"(_p) : "memory"); \
    if (!_done) { \
        asm volatile("{\n\t.reg .pred P1;\n\tWL_%=:\n\tmbarrier.try_wait.parity.acquire.cta.shared::cta.b64 P1, [%0], %1, 0x989680;\n\t@P1 bra.uni WD_%=;\n\tbra.uni WL_%=;\n\tWD_%=:\n\t}" \
            :: "r"(_m), "r"(_p) : "memory"); \
    } } while (0)
#define FENCE_ASYNC() asm volatile("fence.proxy.async.shared::cta;" ::: "memory")

#if defined(__CUDA_ARCH_FEAT_SM103_ALL) || defined(__CUDA_ARCH_FEAT_SM100_ALL)
#define HAS_TCGEN05 1
#else
#define HAS_TCGEN05 0
#endif

#if HAS_TCGEN05
#define TC_ALLOC(smem_addr, ncols) \
    asm volatile("tcgen05.alloc.cta_group::1.sync.aligned.shared::cta.b32 [%0], %1;" :: "r"(smem_addr), "r"(ncols) : "memory")
#define TC_DEALLOC(tmem, ncols) \
    asm volatile("tcgen05.dealloc.cta_group::1.sync.aligned.b32 %0, %1;" :: "r"(tmem), "r"(ncols))
#define TC_RELINQ() \
    asm volatile("tcgen05.relinquish_alloc_permit.cta_group::1.sync.aligned;")
#define TC_COMMIT(mbar) \
    asm volatile("tcgen05.commit.cta_group::1.mbarrier::arrive::one.shared::cluster.b64 [%0];" :: "r"(mbar) : "memory")
#define TC_FENCE_AFTER() asm volatile("tcgen05.fence::after_thread_sync;" ::: "memory")
#define TC_WAIT_LD() asm volatile("tcgen05.wait::ld.sync.aligned;" ::: "memory")

__device__ __forceinline__ void mma_f16_ss(uint32_t d, uint64_t ad, uint64_t bd,
                                           uint32_t idesc, uint32_t en) {
    asm volatile(
        "{\n\t.reg .pred p;\n\tsetp.ne.u32 p, %4, 0;\n\t"
        "tcgen05.mma.cta_group::1.kind::f16 [%0], %1, %2, %3, {%5, %5, %5, %5}, p;\n\t}"
        :: "r"(d), "l"(ad), "l"(bd), "r"(idesc), "r"(en), "r"(0u) : "memory");
}
#define LDTM_X32(r, addr) \
    asm volatile("tcgen05.ld.sync.aligned.32x32b.x32.b32 " \
        "{%0,%1,%2,%3,%4,%5,%6,%7,%8,%9,%10,%11,%12,%13,%14,%15," \
        "%16,%17,%18,%19,%20,%21,%22,%23,%24,%25,%26,%27,%28,%29,%30,%31}, [%32];" \
        : "=r"((r)[0]),"=r"((r)[1]),"=r"((r)[2]),"=r"((r)[3]),"=r"((r)[4]),"=r"((r)[5]),"=r"((r)[6]),"=r"((r)[7]), \
          "=r"((r)[8]),"=r"((r)[9]),"=r"((r)[10]),"=r"((r)[11]),"=r"((r)[12]),"=r"((r)[13]),"=r"((r)[14]),"=r"((r)[15]), \
          "=r"((r)[16]),"=r"((r)[17]),"=r"((r)[18]),"=r"((r)[19]),"=r"((r)[20]),"=r"((r)[21]),"=r"((r)[22]),"=r"((r)[23]), \
          "=r"((r)[24]),"=r"((r)[25]),"=r"((r)[26]),"=r"((r)[27]),"=r"((r)[28]),"=r"((r)[29]),"=r"((r)[30]),"=r"((r)[31]) \
        : "r"(addr))
#endif

// SW128 desc: layout=2, version=1, SBO=64, LBO=1
__device__ __forceinline__ uint64_t make_desc(uint32_t saddr) {
    const uint64_t base = (uint64_t(2) << 61) | (uint64_t(1) << 46) | (uint64_t(64) << 32) | (uint64_t(1) << 16);
    return base | ((uint64_t)(saddr >> 4) & 0x3FFF);
}
// idesc: F32 accum, BF16 a/b, N=256, M=128
#define KV_IDESC ((1u << 4) | (1u << 7) | (1u << 10) | (32u << 17) | (8u << 24))

// ---------------- 1. LN + bf16 hi/lo split of A = concat(xn, ln) ----------------
__global__ void __launch_bounds__(256) prep_a_kernel(
    const float* __restrict__ x, const float* __restrict__ lat,
    const float* __restrict__ gm, const float* __restrict__ bm,
    const float* __restrict__ gl, const float* __restrict__ bl)
{
    int row = blockIdx.x;
    int tid = threadIdx.x;
    bool isx = row < ROWS_X;
    const float* src = isx ? (x + (size_t)row * DM)
                           : (lat + (size_t)(row - ROWS_X) * DM);
    float4 v = reinterpret_cast<const float4*>(src)[tid];
    float s  = v.x + v.y + v.z + v.w;
    float sq = v.x * v.x + v.y * v.y + v.z * v.z + v.w * v.w;
    s = warpSum(s); sq = warpSum(sq);
    __shared__ float sh[2][8];
    int w = tid >> 5, lane = tid & 31;
    if (lane == 0) { sh[0][w] = s; sh[1][w] = sq; }
    __syncthreads();
    float tot = 0.f, totq = 0.f;
#pragma unroll
    for (int i = 0; i < 8; i++) { tot += sh[0][i]; totq += sh[1][i]; }
    float mean = tot * (1.0f / 1024.0f);
    float var  = totq * (1.0f / 1024.0f) - mean * mean;
    float rstd = rsqrtf(var + 1e-5f);

    const float* gp = isx ? gm : gl;
    const float* bp = isx ? bm : bl;
    float4 g4 = reinterpret_cast<const float4*>(gp)[tid];
    float4 b4 = reinterpret_cast<const float4*>(bp)[tid];
    float4 o;
    o.x = (v.x - mean) * rstd * g4.x + b4.x;
    o.y = (v.y - mean) * rstd * g4.y + b4.y;
    o.z = (v.z - mean) * rstd * g4.z + b4.z;
    o.w = (v.w - mean) * rstd * g4.w + b4.w;

    int arow;
    if (isx) {
        int bb = row >> 13, ss = row & 8191;
        arow = bb * S_TOT + ss;
    } else {
        int lr = row - ROWS_X;
        int bb = lr >> 6, j = lr & 63;
        arow = bb * S_TOT + MM + j;
        reinterpret_cast<float4*>(g_ln + (size_t)lr * DM)[tid] = o;
    }
    __nv_bfloat16 hx = __float2bfloat16(o.x), hy = __float2bfloat16(o.y);
    __nv_bfloat16 hz = __float2bfloat16(o.z), hw = __float2bfloat16(o.w);
    float rx = o.x - __bfloat162float(hx), ry = o.y - __bfloat162float(hy);
    float rz = o.z - __bfloat162float(hz), rw = o.w - __bfloat162float(hw);
    __nv_bfloat162 h01 = __nv_bfloat162(hx, hy), h23 = __nv_bfloat162(hz, hw);
    __nv_bfloat162 l01 = __floats2bfloat162_rn(rx, ry), l23 = __floats2bfloat162_rn(rz, rw);
    uint2 uh, ul;
    uh.x = *reinterpret_cast<uint32_t*>(&h01); uh.y = *reinterpret_cast<uint32_t*>(&h23);
    ul.x = *reinterpret_cast<uint32_t*>(&l01); ul.y = *reinterpret_cast<uint32_t*>(&l23);
    reinterpret_cast<uint2*>(g_Ahi + (size_t)arow * DM)[tid] = uh;
    reinterpret_cast<uint2*>(g_Alo + (size_t)arow * DM)[tid] = ul;
}

// ---------------- 2. W transpose + hi/lo split ----------------
__global__ void __launch_bounds__(256) prep_w_kernel(const float* __restrict__ Wkv)
{
    int n = blockIdx.x;
    for (int k = threadIdx.x; k < DM; k += 256) {
        float wv = Wkv[(size_t)k * (2 * IND) + n];
        __nv_bfloat16 hi = __float2bfloat16(wv);
        float r = wv - __bfloat162float(hi);
        g_Whi[(size_t)n * DM + k] = hi;
        g_Wlo[(size_t)n * DM + k] = __float2bfloat16(r);
    }
}

// ---------------- 3. q = ln @ Wq ----------------
__global__ void __launch_bounds__(256) q_gemm_kernel(const float* __restrict__ Wq)
{
    int o = blockIdx.x * 256 + threadIdx.x;
    int n  = o & 511;
    int rg = o >> 9;
    float a0 = 0.f, a1 = 0.f, a2 = 0.f, a3 = 0.f;
    const float* l0 = g_ln + (size_t)rg * DM;
    const float* l1 = g_ln + (size_t)(rg + 64) * DM;
    const float* l2 = g_ln + (size_t)(rg + 128) * DM;
    const float* l3 = g_ln + (size_t)(rg + 192) * DM;
    for (int k = 0; k < DM; k++) {
        float wv = __ldg(Wq + (size_t)k * IND + n);
        a0 += l0[k] * wv; a1 += l1[k] * wv; a2 += l2[k] * wv; a3 += l3[k] * wv;
    }
    g_q[(size_t)rg * IND + n]         = a0;
    g_q[(size_t)(rg + 64) * IND + n]  = a1;
    g_q[(size_t)(rg + 128) * IND + n] = a2;
    g_q[(size_t)(rg + 192) * IND + n] = a3;
}

// ---------------- 4. KV GEMM on tcgen05, cp.async pipelined ----------------
// grid (4 ntiles, 258 mtiles), 256 threads. CTA tile M=128, N=256.
// Per k-chunk (K=64): 3 matmuls (Ahi*Whi, Ahi*Wlo, Alo*Whi). 16 chunks.
// 2-stage cp.async double buffer; MMA-completion mbarrier gates stage reuse.
#define OFF_AHI 0
#define OFF_ALO 16384
#define OFF_WHI 32768
#define OFF_WLO 65536
#define STAGE_BYTES 98304
#define SM_TM   0
#define SM_MB   64
#define SM_DATA 1024
#define SM_TOT  (SM_DATA + 2 * STAGE_BYTES)

__global__ void __launch_bounds__(256) kv_gemm_tc()
{
#if HAS_TCGEN05
    extern __shared__ char smem[];
    uint32_t sb = smem_u32(smem);
    int tid = threadIdx.x, wid = tid >> 5;
    int ntile = blockIdx.x, mtile = blockIdx.y;

    if (wid == 0) { TC_ALLOC(sb + SM_TM, 256); TC_RELINQ(); }
    if (tid == 0) { MBAR_INIT(sb + SM_MB, 1); MBAR_INIT(sb + SM_MB + 8, 1); }
    __syncthreads();
    uint32_t tmem;
    asm volatile("ld.shared.b32 %0, [%1];" : "=r"(tmem) : "r"(sb + SM_TM));

    const char* Ah = (const char*)g_Ahi + (size_t)(mtile * 128) * 2048;
    const char* Al = (const char*)g_Alo + (size_t)(mtile * 128) * 2048;
    const char* Wh = (const char*)g_Whi + (size_t)(ntile * 256) * 2048;
    const char* Wl = (const char*)g_Wlo + (size_t)(ntile * 256) * 2048;

    // per-thread copy offsets (kc-invariant)
    uint32_t a_src[4], a_dst[4], w_src[8], w_dst[8];
#pragma unroll
    for (int it = 0; it < 4; it++) {
        int idx = it * 256 + tid;
        int row = idx >> 3, cb = idx & 7;
        a_src[it] = (uint32_t)(row * 2048 + cb * 16);
        uint32_t bo = (uint32_t)(row * 128 + cb * 16);
        a_dst[it] = bo ^ ((bo >> 3) & 0x70);
    }
#pragma unroll
    for (int it = 0; it < 8; it++) {
        int idx = it * 256 + tid;
        int row = idx >> 3, cb = idx & 7;
        w_src[it] = (uint32_t)(row * 2048 + cb * 16);
        uint32_t bo = (uint32_t)(row * 128 + cb * 16);
        w_dst[it] = bo ^ ((bo >> 3) & 0x70);
    }

#define FILL_STAGE(st, kc) do { \
        uint32_t sbase = sb + SM_DATA + (st) * STAGE_BYTES; \
        uint32_t koff = (uint32_t)(kc) * 128; \
        _Pragma("unroll") \
        for (int it = 0; it < 4; it++) { \
            cp16(sbase + OFF_AHI + a_dst[it], Ah + a_src[it] + koff); \
            cp16(sbase + OFF_ALO + a_dst[it], Al + a_src[it] + koff); \
        } \
        _Pragma("unroll") \
        for (int it = 0; it < 8; it++) { \
            cp16(sbase + OFF_WHI + w_dst[it], Wh + w_src[it] + koff); \
            cp16(sbase + OFF_WLO + w_dst[it], Wl + w_src[it] + koff); \
        } \
        CP_COMMIT(); \
    } while (0)

    FILL_STAGE(0, 0);
    FILL_STAGE(1, 1);

    int pc[2] = {0, 0};

    for (int kc = 0; kc < 16; kc++) {
        int st = kc & 1;
        if (kc == 15) { CP_WAIT(0); } else { CP_WAIT(1); }
        FENCE_ASYNC();
        __syncthreads();

        if (wid == 0 && elect_one()) {
            uint32_t sbase = sb + SM_DATA + st * STAGE_BYTES;
            uint64_t ahd = make_desc(sbase + OFF_AHI);
            uint64_t ald = make_desc(sbase + OFF_ALO);
            uint64_t whd = make_desc(sbase + OFF_WHI);
            uint64_t wld = make_desc(sbase + OFF_WLO);
#pragma unroll
            for (int s = 0; s < 4; s++) {
                uint32_t en = !(kc == 0 && s == 0);
                mma_f16_ss(tmem, ahd + s * 2, whd + s * 2, KV_IDESC, en);
            }
#pragma unroll
            for (int s = 0; s < 4; s++)
                mma_f16_ss(tmem, ahd + s * 2, wld + s * 2, KV_IDESC, 1);
#pragma unroll
            for (int s = 0; s < 4; s++)
                mma_f16_ss(tmem, ald + s * 2, whd + s * 2, KV_IDESC, 1);
            TC_COMMIT(sb + SM_MB + st * 8);
        }

        if (kc < 14) {
            MBAR_WAIT(sb + SM_MB + st * 8, (uint32_t)(pc[st] & 1));
            pc[st]++;
            FILL_STAGE(st, kc + 2);
        }
    }

    MBAR_WAIT(sb + SM_MB,     (uint32_t)(pc[0] & 1));
    MBAR_WAIT(sb + SM_MB + 8, (uint32_t)(pc[1] & 1));
    TC_FENCE_AFTER();

    if (wid < 4) {
        int lane = tid & 31;
        size_t rowg = (size_t)(mtile * 128 + wid * 32 + lane);
        float* dst = g_kv + rowg * (2 * IND) + ntile * 256;
#pragma unroll
        for (int cb = 0; cb < 8; cb++) {
            uint32_t r[32];
            LDTM_X32(r, tmem + cb * 32);
            TC_WAIT_LD();
#pragma unroll
            for (int j = 0; j < 32; j += 4) {
                uint4 v;
                v.x = r[j]; v.y = r[j + 1]; v.z = r[j + 2]; v.w = r[j + 3];
                *reinterpret_cast<uint4*>(dst + cb * 32 + j) = v;
            }
        }
    }
    __syncthreads();
    if (wid == 0) TC_DEALLOC(tmem, 256);
#undef FILL_STAGE
#else
    // generic-PTX fallback (never executed on sm_103a; exact cubin preferred)
    int tid = threadIdx.x;
    int ntile = blockIdx.x, mtile = blockIdx.y;
    for (int i = tid; i < 128 * 256; i += 256) {
        int r = i >> 8, cc = i & 255;
        size_t row = (size_t)mtile * 128 + r;
        size_t col = (size_t)ntile * 256 + cc;
        float acc = 0.f;
        for (int k = 0; k < DM; k++) {
            float a = __bfloat162float(g_Ahi[row * DM + k]) + __bfloat162float(g_Alo[row * DM + k]);
            float w = __bfloat162float(g_Whi[col * DM + k]) + __bfloat162float(g_Wlo[col * DM + k]);
            acc += a * w;
        }
        g_kv[row * (2 * IND) + col] = acc;
    }
#endif
}

// ---------------- 5. split-KV flash attention (vectorized, cp.async) ----------------
// grid (NCHUNK, 32), 512 threads = 16 warps; warp owns 4 q-rows; lanes = keys for QK,
// lanes = d-pairs for PV. Double-buffered 32-key K/V tiles via cp.async.
// Dynamic smem (floats): QS 4096 | KS 2*32*68 | VS 2*32*64 | PS 64*36
#define AQ_QS 0
#define AQ_KS 4096
#define AQ_VS 8448
#define AQ_PS 12544
#define AQ_TOT_F 14848
#define KS_STRIDE 68

__global__ void __launch_bounds__(512) attn_kernel()
{
    extern __shared__ float sm[];
    float* QS = sm + AQ_QS;
    float* KS = sm + AQ_KS;
    float* VS = sm + AQ_VS;
    float* PS = sm + AQ_PS;
    uint32_t ks_u = smem_u32(KS);
    uint32_t vs_u = smem_u32(VS);

    int bh = blockIdx.y;
    int b = bh >> 3, h = bh & 7;
    int tid = threadIdx.x, w = tid >> 5, lane = tid & 31;

    // load Q (scaled by sqrt(64) = 8)
#pragma unroll
    for (int j = 0; j < 2; j++) {
        int idx = tid + j * 512;                  // 0..1023 float4s
        int row = idx >> 4, d = (idx & 15) * 4;
        float4 q = *reinterpret_cast<const float4*>(
            g_q + (size_t)(b * 64 + row) * IND + h * 64 + d);
        q.x *= 8.f; q.y *= 8.f; q.z *= 8.f; q.w *= 8.f;
        *reinterpret_cast<float4*>(QS + row * 64 + d) = q;
    }

    int s0beg = blockIdx.x * 512;
    int s0end = min(S_TOT, s0beg + 512);
    int ntiles = (s0end - s0beg) >> 5;

    // cp.async tile copy mapping: key = tid>>4 (0..31), d4 = tid&15
    int ckey = tid >> 4, cd4 = tid & 15;
    const char* kv_base = (const char*)(g_kv + (size_t)(b * S_TOT) * (2 * IND)) + h * 256 + cd4 * 16;

#define ISSUE_TILE(t, buf) do { \
        const char* srcr = kv_base + (size_t)(s0beg + (t) * 32 + ckey) * 4096; \
        cp16(ks_u + ((buf) * 2176 + ckey * KS_STRIDE + cd4 * 4) * 4, srcr); \
        cp16(vs_u + ((buf) * 2048 + ckey * 64 + cd4 * 4) * 4, srcr + 2048); \
        CP_COMMIT(); \
    } while (0)

    ISSUE_TILE(0, 0);

    int r0 = w * 4;
    float m[4], l[4];
    float2 o[4];
#pragma unroll
    for (int r = 0; r < 4; r++) { m[r] = -3.0e38f; l[r] = 0.f; o[r] = make_float2(0.f, 0.f); }
    int dlo = lane * 2;

    for (int t = 0; t < ntiles; t++) {
        int buf = t & 1;
        if (t + 1 < ntiles) { ISSUE_TILE(t + 1, (t + 1) & 1); CP_WAIT(1); }
        else                { CP_WAIT(0); }
        __syncthreads();

        // ---- QK: lanes = keys ----
        float s[4] = {0.f, 0.f, 0.f, 0.f};
        const float* kr = KS + buf * 2176 + lane * KS_STRIDE;
#pragma unroll
        for (int db = 0; db < 16; db++) {
            float4 kf = *reinterpret_cast<const float4*>(kr + db * 4);
#pragma unroll
            for (int r = 0; r < 4; r++) {
                float4 qf = *reinterpret_cast<const float4*>(QS + (r0 + r) * 64 + db * 4);
                s[r] += qf.x * kf.x + qf.y * kf.y + qf.z * kf.z + qf.w * kf.w;
            }
        }

        // ---- softmax update + stage P ----
        float alpha[4];
#pragma unroll
        for (int r = 0; r < 4; r++) {
            float tm = warpMax(s[r]);
            float mn = fmaxf(m[r], tm);
            float p  = __expf(s[r] - mn);
            alpha[r] = __expf(m[r] - mn);
            float psum = warpSum(p);
            l[r] = l[r] * alpha[r] + psum;
            m[r] = mn;
            PS[(r0 + r) * 36 + lane] = p;
        }
        __syncwarp();

        // ---- PV: lanes = d-pairs ----
        const float* vb = VS + buf * 2048;
#pragma unroll
        for (int r = 0; r < 4; r++) {
            float ax = o[r].x * alpha[r];
            float ay = o[r].y * alpha[r];
            const float* pr = PS + (r0 + r) * 36;
#pragma unroll
            for (int k4 = 0; k4 < 8; k4++) {
                float4 pb = *reinterpret_cast<const float4*>(pr + k4 * 4);
                float2 v0 = *reinterpret_cast<const float2*>(vb + (k4 * 4 + 0) * 64 + dlo);
                float2 v1 = *reinterpret_cast<const float2*>(vb + (k4 * 4 + 1) * 64 + dlo);
                float2 v2 = *reinterpret_cast<const float2*>(vb + (k4 * 4 + 2) * 64 + dlo);
                float2 v3 = *reinterpret_cast<const float2*>(vb + (k4 * 4 + 3) * 64 + dlo);
                ax += pb.x * v0.x + pb.y * v1.x + pb.z * v2.x + pb.w * v3.x;
                ay += pb.x * v0.y + pb.y * v1.y + pb.z * v2.y + pb.w * v3.y;
            }
            o[r].x = ax; o[r].y = ay;
        }
        __syncthreads();
    }

    int c = bh * NCHUNK + blockIdx.x;
#pragma unroll
    for (int r = 0; r < 4; r++) {
        int row = r0 + r;
        *reinterpret_cast<float2*>(g_po + ((size_t)c * 64 + row) * 64 + dlo) = o[r];
        if (lane == 0) { g_pm[c * 64 + row] = m[r]; g_pl[c * 64 + row] = l[r]; }
    }
#undef ISSUE_TILE
}

// ---------------- 6. merge split-KV partials ----------------
__global__ void __launch_bounds__(256) merge_kernel()
{
    int bh = blockIdx.x;
    int b = bh >> 3, h = bh & 7;
    int tid = threadIdx.x;
    int row = tid >> 2;
    int dp  = (tid & 3) * 16;

    float mx = -3.0e38f;
    for (int c = 0; c < NCHUNK; c++)
        mx = fmaxf(mx, g_pm[(bh * NCHUNK + c) * 64 + row]);

    float Ls = 0.f;
    float acc[16];
#pragma unroll
    for (int j = 0; j < 16; j++) acc[j] = 0.f;

    for (int c = 0; c < NCHUNK; c++) {
        int idx = (bh * NCHUNK + c) * 64 + row;
        float wgt = __expf(g_pm[idx] - mx);
        Ls += wgt * g_pl[idx];
        const float* po = g_po + (size_t)idx * 64 + dp;
#pragma unroll
        for (int j = 0; j < 16; j++) acc[j] += wgt * po[j];
    }
    float inv = 1.0f / Ls;
    float* dst = g_ao + (size_t)(b * 64 + row) * IND + h * 64 + dp;
#pragma unroll
    for (int j = 0; j < 16; j++) dst[j] = acc[j] * inv;
}

// ---------------- 7. out = attn_out @ Wout ----------------
__global__ void __launch_bounds__(256) out_gemm_kernel(
    const float* __restrict__ Wout, float* __restrict__ out)
{
    int o = blockIdx.x * 256 + threadIdx.x;
    int n  = o & 1023;
    int rg = o >> 10;
    float a0 = 0.f, a1 = 0.f, a2 = 0.f, a3 = 0.f;
    const float* l0 = g_ao + (size_t)rg * IND;
    const float* l1 = g_ao + (size_t)(rg + 64) * IND;
    const float* l2 = g_ao + (size_t)(rg + 128) * IND;
    const float* l3 = g_ao + (size_t)(rg + 192) * IND;
    for (int k = 0; k < IND; k++) {
        float wv = __ldg(Wout + (size_t)k * DM + n);
        a0 += l0[k] * wv; a1 += l1[k] * wv; a2 += l2[k] * wv; a3 += l3[k] * wv;
    }
    out[(size_t)rg * DM + n]         = a0;
    out[(size_t)(rg + 64) * DM + n]  = a1;
    out[(size_t)(rg + 128) * DM + n] = a2;
    out[(size_t)(rg + 192) * DM + n] = a3;
}

// ---------------- launch ----------------
extern "C" void kernel_launch(void* const* d_in, const int* in_sizes, int n_in,
                              void* d_out, int out_size)
{
    const float* x    = (const float*)d_in[0];
    const float* lat  = (const float*)d_in[1];
    const float* Wq   = (const float*)d_in[2];
    const float* Wkv  = (const float*)d_in[3];
    const float* Wout = (const float*)d_in[4];
    const float* gm   = (const float*)d_in[5];
    const float* bm   = (const float*)d_in[6];
    const float* gl   = (const float*)d_in[7];
    const float* bl   = (const float*)d_in[8];
    float* out = (float*)d_out;

    cudaFuncSetAttribute(kv_gemm_tc, cudaFuncAttributeMaxDynamicSharedMemorySize, SM_TOT);
    cudaFuncSetAttribute(attn_kernel, cudaFuncAttributeMaxDynamicSharedMemorySize, AQ_TOT_F * 4);

    prep_a_kernel<<<ROWS_KV, 256>>>(x, lat, gm, bm, gl, bl);
    prep_w_kernel<<<DM, 256>>>(Wkv);
    q_gemm_kernel<<<32768 / 256, 256>>>(Wq);
    kv_gemm_tc<<<dim3(4, 258), 256, SM_TOT>>>();
    attn_kernel<<<dim3(NCHUNK, 32), 512, AQ_TOT_F * 4>>>();
    merge_kernel<<<32, 256>>>();
    out_gemm_kernel<<<65536 / 256, 256>>>(Wout, out);
}